// round 1
// baseline (speedup 1.0000x reference)
#include <cuda_runtime.h>
#include <math.h>

// ---------------------------------------------------------------------------
// Problem constants (MultiHeadAttention: B=4, S=2048, D=1024, H=16, DQKV=64)
// ---------------------------------------------------------------------------
constexpr int CB = 4;
constexpr int CS = 2048;
constexpr int CD = 1024;
constexpr int CH = 16;
constexpr int CE = 64;                 // DQKV
constexpr int MROWS = CB * CS;         // 8192

// Scratch (device globals: allocation-free per harness rules)
__device__ float g_Q[MROWS * CD];
__device__ float g_K[MROWS * CD];
__device__ float g_V[MROWS * CD];
__device__ float g_C[MROWS * CD];

// ---------------------------------------------------------------------------
// GEMM:  C[m][n] = sum_k A[m][k] * W[n][k] + bias[n]
// A: [M,K] row-major, W: [N,K] row-major (torch Linear layout), exact tiles.
// BM=128, BN=128, BK=16, 256 threads, 8x8 per-thread register tile.
// ---------------------------------------------------------------------------
__global__ __launch_bounds__(256) void gemm_bias_kernel(
    const float* __restrict__ A, const float* __restrict__ W,
    const float* __restrict__ bias, float* __restrict__ C,
    int Mdim, int Ndim, int Kdim)
{
    constexpr int BM = 128, BN = 128, BK = 16;
    __shared__ float As[BK][BM + 4];
    __shared__ float Ws[BK][BN + 4];

    const int tid = threadIdx.x;
    const int tx = tid & 15;       // 0..15
    const int ty = tid >> 4;       // 0..15
    const int bm = blockIdx.y * BM;
    const int bn = blockIdx.x * BN;

    float acc[8][8];
    #pragma unroll
    for (int i = 0; i < 8; i++)
        #pragma unroll
        for (int j = 0; j < 8; j++) acc[i][j] = 0.0f;

    for (int k0 = 0; k0 < Kdim; k0 += BK) {
        // Load tiles (transposed into smem): 2 float4 per thread per matrix.
        #pragma unroll
        for (int q = 0; q < 2; q++) {
            int f   = q * 256 + tid;     // 0..511
            int row = f >> 2;            // 0..127
            int kk  = (f & 3) * 4;       // 0,4,8,12
            float4 av = *reinterpret_cast<const float4*>(
                &A[(size_t)(bm + row) * Kdim + k0 + kk]);
            As[kk + 0][row] = av.x; As[kk + 1][row] = av.y;
            As[kk + 2][row] = av.z; As[kk + 3][row] = av.w;
            float4 wv = *reinterpret_cast<const float4*>(
                &W[(size_t)(bn + row) * Kdim + k0 + kk]);
            Ws[kk + 0][row] = wv.x; Ws[kk + 1][row] = wv.y;
            Ws[kk + 2][row] = wv.z; Ws[kk + 3][row] = wv.w;
        }
        __syncthreads();

        #pragma unroll
        for (int kk = 0; kk < BK; kk++) {
            float a[8], b[8];
            float4 a0 = *reinterpret_cast<const float4*>(&As[kk][ty * 8]);
            float4 a1 = *reinterpret_cast<const float4*>(&As[kk][ty * 8 + 4]);
            a[0]=a0.x; a[1]=a0.y; a[2]=a0.z; a[3]=a0.w;
            a[4]=a1.x; a[5]=a1.y; a[6]=a1.z; a[7]=a1.w;
            float4 b0 = *reinterpret_cast<const float4*>(&Ws[kk][tx * 8]);
            float4 b1 = *reinterpret_cast<const float4*>(&Ws[kk][tx * 8 + 4]);
            b[0]=b0.x; b[1]=b0.y; b[2]=b0.z; b[3]=b0.w;
            b[4]=b1.x; b[5]=b1.y; b[6]=b1.z; b[7]=b1.w;
            #pragma unroll
            for (int i = 0; i < 8; i++)
                #pragma unroll
                for (int j = 0; j < 8; j++)
                    acc[i][j] = fmaf(a[i], b[j], acc[i][j]);
        }
        __syncthreads();
    }

    // Epilogue: add bias, vectorized stores.
    float bl[8];
    #pragma unroll
    for (int j = 0; j < 8; j += 4) {
        float4 bv = *reinterpret_cast<const float4*>(&bias[bn + tx * 8 + j]);
        bl[j+0]=bv.x; bl[j+1]=bv.y; bl[j+2]=bv.z; bl[j+3]=bv.w;
    }
    #pragma unroll
    for (int i = 0; i < 8; i++) {
        int m = bm + ty * 8 + i;
        #pragma unroll
        for (int j = 0; j < 8; j += 4) {
            int n = bn + tx * 8 + j;
            float4 o;
            o.x = acc[i][j+0] + bl[j+0];
            o.y = acc[i][j+1] + bl[j+1];
            o.z = acc[i][j+2] + bl[j+2];
            o.w = acc[i][j+3] + bl[j+3];
            *reinterpret_cast<float4*>(&C[(size_t)m * Ndim + n]) = o;
        }
    }
}

// ---------------------------------------------------------------------------
// Flash attention (fp32, online softmax).
// One block per (b, h, 128-query tile). 256 threads (tx 0..15, ty 0..15).
// Per key-tile of 64: S = Q K^T / 8 -> softmax update -> O += P V.
// Thread (ty,tx) owns rows 8*ty..8*ty+7, cols 4*tx..4*tx+3 of both S and O.
// Smem (dynamic, ~100 KB): Qt[64][132], Kt[64][68], Vs[64][68], Pt[64][132].
// ---------------------------------------------------------------------------
constexpr int BQ  = 128;
constexpr int BKT = 64;
constexpr int QT_STRIDE = BQ + 4;   // 132
constexpr int KT_STRIDE = BKT + 4;  // 68
constexpr int VS_STRIDE = CE + 4;   // 68
constexpr int ATTN_SMEM_FLOATS =
    CE * QT_STRIDE + CE * KT_STRIDE + BKT * VS_STRIDE + BKT * QT_STRIDE;
constexpr size_t ATTN_SMEM_BYTES = ATTN_SMEM_FLOATS * sizeof(float);

__global__ __launch_bounds__(256) void attn_kernel(
    const float* __restrict__ Qg, const float* __restrict__ Kg,
    const float* __restrict__ Vg, float* __restrict__ Ctx)
{
    extern __shared__ float sm[];
    float (*Qt)[QT_STRIDE] = reinterpret_cast<float(*)[QT_STRIDE]>(sm);
    float (*Kt)[KT_STRIDE] = reinterpret_cast<float(*)[KT_STRIDE]>(sm + CE * QT_STRIDE);
    float (*Vs)[VS_STRIDE] = reinterpret_cast<float(*)[VS_STRIDE]>(sm + CE * QT_STRIDE + CE * KT_STRIDE);
    float (*Pt)[QT_STRIDE] = reinterpret_cast<float(*)[QT_STRIDE]>(sm + CE * QT_STRIDE + CE * KT_STRIDE + BKT * VS_STRIDE);

    const int tid = threadIdx.x;
    const int tx = tid & 15;
    const int ty = tid >> 4;
    const int q0 = blockIdx.x * BQ;
    const int bh = blockIdx.y;
    const int b  = bh / CH;
    const int h  = bh % CH;
    const size_t base = (size_t)b * CS * CD + (size_t)h * CE;  // + row*CD + e

    // Load Q tile transposed: 2048 float4, 8 per thread.
    #pragma unroll
    for (int q = 0; q < 8; q++) {
        int f   = q * 256 + tid;   // 0..2047
        int row = f >> 4;          // 0..127
        int e0  = (f & 15) * 4;    // 0..60
        float4 v = *reinterpret_cast<const float4*>(
            &Qg[base + (size_t)(q0 + row) * CD + e0]);
        Qt[e0 + 0][row] = v.x; Qt[e0 + 1][row] = v.y;
        Qt[e0 + 2][row] = v.z; Qt[e0 + 3][row] = v.w;
    }

    float o[8][4];
    float mrow[8], lrow[8];
    #pragma unroll
    for (int i = 0; i < 8; i++) {
        mrow[i] = -1e30f; lrow[i] = 0.0f;
        #pragma unroll
        for (int c = 0; c < 4; c++) o[i][c] = 0.0f;
    }

    const float scale = 0.125f;  // 1/sqrt(64)

    for (int kt = 0; kt < CS; kt += BKT) {
        __syncthreads();  // previous GEMM2 reads of Kt/Vs/Pt complete; Q load visible

        // Load K (transposed) and V (natural): 1024 float4 each, 4 per thread.
        #pragma unroll
        for (int q = 0; q < 4; q++) {
            int f   = q * 256 + tid;   // 0..1023
            int row = f >> 4;          // 0..63
            int e0  = (f & 15) * 4;
            size_t g = base + (size_t)(kt + row) * CD + e0;
            float4 kv = *reinterpret_cast<const float4*>(&Kg[g]);
            Kt[e0 + 0][row] = kv.x; Kt[e0 + 1][row] = kv.y;
            Kt[e0 + 2][row] = kv.z; Kt[e0 + 3][row] = kv.w;
            float4 vv = *reinterpret_cast<const float4*>(&Vg[g]);
            *reinterpret_cast<float4*>(&Vs[row][e0]) = vv;
        }
        __syncthreads();

        // GEMM1: s[i][c] = sum_e Qt[e][8ty+i] * Kt[e][4tx+c]
        float s[8][4];
        #pragma unroll
        for (int i = 0; i < 8; i++)
            #pragma unroll
            for (int c = 0; c < 4; c++) s[i][c] = 0.0f;

        #pragma unroll 4
        for (int e = 0; e < CE; e++) {
            float a[8], bb[4];
            float4 a0 = *reinterpret_cast<const float4*>(&Qt[e][ty * 8]);
            float4 a1 = *reinterpret_cast<const float4*>(&Qt[e][ty * 8 + 4]);
            a[0]=a0.x; a[1]=a0.y; a[2]=a0.z; a[3]=a0.w;
            a[4]=a1.x; a[5]=a1.y; a[6]=a1.z; a[7]=a1.w;
            float4 b4 = *reinterpret_cast<const float4*>(&Kt[e][tx * 4]);
            bb[0]=b4.x; bb[1]=b4.y; bb[2]=b4.z; bb[3]=b4.w;
            #pragma unroll
            for (int i = 0; i < 8; i++)
                #pragma unroll
                for (int c = 0; c < 4; c++)
                    s[i][c] = fmaf(a[i], bb[c], s[i][c]);
        }

        // Online softmax update per owned row; P written transposed to smem.
        #pragma unroll
        for (int i = 0; i < 8; i++) {
            float tm = -1e30f;
            #pragma unroll
            for (int c = 0; c < 4; c++) { s[i][c] *= scale; tm = fmaxf(tm, s[i][c]); }
            #pragma unroll
            for (int off = 8; off >= 1; off >>= 1)
                tm = fmaxf(tm, __shfl_xor_sync(0xffffffffu, tm, off));
            float mnew  = fmaxf(mrow[i], tm);
            float alpha = __expf(mrow[i] - mnew);
            mrow[i] = mnew;
            float p[4];
            float rs = 0.0f;
            #pragma unroll
            for (int c = 0; c < 4; c++) { p[c] = __expf(s[i][c] - mnew); rs += p[c]; }
            #pragma unroll
            for (int off = 8; off >= 1; off >>= 1)
                rs += __shfl_xor_sync(0xffffffffu, rs, off);
            lrow[i] = lrow[i] * alpha + rs;
            #pragma unroll
            for (int c = 0; c < 4; c++) {
                o[i][c] *= alpha;
                Pt[tx * 4 + c][ty * 8 + i] = p[c];
            }
        }
        __syncthreads();

        // GEMM2: o[i][c] += sum_j Pt[j][8ty+i] * Vs[j][4tx+c]
        #pragma unroll 4
        for (int j = 0; j < BKT; j++) {
            float a[8], vv[4];
            float4 p0 = *reinterpret_cast<const float4*>(&Pt[j][ty * 8]);
            float4 p1 = *reinterpret_cast<const float4*>(&Pt[j][ty * 8 + 4]);
            a[0]=p0.x; a[1]=p0.y; a[2]=p0.z; a[3]=p0.w;
            a[4]=p1.x; a[5]=p1.y; a[6]=p1.z; a[7]=p1.w;
            float4 v4 = *reinterpret_cast<const float4*>(&Vs[j][tx * 4]);
            vv[0]=v4.x; vv[1]=v4.y; vv[2]=v4.z; vv[3]=v4.w;
            #pragma unroll
            for (int i = 0; i < 8; i++)
                #pragma unroll
                for (int c = 0; c < 4; c++)
                    o[i][c] = fmaf(a[i], vv[c], o[i][c]);
        }
    }

    // Epilogue: normalize and write context (layout [b][s][h*64+e]).
    #pragma unroll
    for (int i = 0; i < 8; i++) {
        float inv = 1.0f / lrow[i];
        float4 ov;
        ov.x = o[i][0] * inv; ov.y = o[i][1] * inv;
        ov.z = o[i][2] * inv; ov.w = o[i][3] * inv;
        *reinterpret_cast<float4*>(
            &Ctx[base + (size_t)(q0 + ty * 8 + i) * CD + tx * 4]) = ov;
    }
}

// ---------------------------------------------------------------------------
// Launch: 3 projection GEMMs -> attention -> output GEMM (all one stream,
// graph-capturable, allocation-free).
// ---------------------------------------------------------------------------
extern "C" void kernel_launch(void* const* d_in, const int* in_sizes, int n_in,
                              void* d_out, int out_size)
{
    const float* query = (const float*)d_in[0];
    const float* key   = (const float*)d_in[1];
    const float* value = (const float*)d_in[2];
    const float* wq    = (const float*)d_in[3];
    const float* bq    = (const float*)d_in[4];
    const float* wk    = (const float*)d_in[5];
    const float* bk    = (const float*)d_in[6];
    const float* wv    = (const float*)d_in[7];
    const float* bv    = (const float*)d_in[8];
    const float* wo    = (const float*)d_in[9];
    const float* bo    = (const float*)d_in[10];
    float* out = (float*)d_out;

    float *Qd, *Kd, *Vd, *Cd;
    cudaGetSymbolAddress((void**)&Qd, g_Q);
    cudaGetSymbolAddress((void**)&Kd, g_K);
    cudaGetSymbolAddress((void**)&Vd, g_V);
    cudaGetSymbolAddress((void**)&Cd, g_C);

    cudaFuncSetAttribute(attn_kernel,
                         cudaFuncAttributeMaxDynamicSharedMemorySize,
                         (int)ATTN_SMEM_BYTES);

    dim3 gemm_grid(CD / 128, MROWS / 128);  // (8, 64)

    // Q/K/V projections: [8192,1024] x [1024,1024]^T + bias
    gemm_bias_kernel<<<gemm_grid, 256>>>(query, wq, bq, Qd, MROWS, CD, CD);
    gemm_bias_kernel<<<gemm_grid, 256>>>(key,   wk, bk, Kd, MROWS, CD, CD);
    gemm_bias_kernel<<<gemm_grid, 256>>>(value, wv, bv, Vd, MROWS, CD, CD);

    // Attention: 16 query tiles x 64 (b,h) pairs
    attn_kernel<<<dim3(CS / BQ, CB * CH), 256, ATTN_SMEM_BYTES>>>(Qd, Kd, Vd, Cd);

    // Output projection: out = ctx @ wo^T + bo
    gemm_bias_kernel<<<gemm_grid, 256>>>(Cd, wo, bo, out, MROWS, CD, CD);
}

// round 3
// speedup vs baseline: 2.7943x; 2.7943x over previous
#include <cuda_runtime.h>
#include <cuda_bf16.h>
#include <cstdint>

// ---------------------------------------------------------------------------
// Problem constants (B=4, S=2048, D=1024, H=16, DQKV=64)
// ---------------------------------------------------------------------------
constexpr int CB = 4;
constexpr int CS = 2048;
constexpr int CD = 1024;
constexpr int CH = 16;
constexpr int CE = 64;
constexpr int MROWS = CB * CS;   // 8192

// ---------------------------------------------------------------------------
// Device scratch (allocation-free)
// ---------------------------------------------------------------------------
__device__ __nv_bfloat16 g_xqh[MROWS * CD], g_xql[MROWS * CD];   // input query split
__device__ __nv_bfloat16 g_xkh[MROWS * CD], g_xkl[MROWS * CD];   // input key split
__device__ __nv_bfloat16 g_xvh[MROWS * CD], g_xvl[MROWS * CD];   // input value split
__device__ __nv_bfloat16 g_wqh[CD * CD], g_wql[CD * CD];
__device__ __nv_bfloat16 g_wkh[CD * CD], g_wkl[CD * CD];
__device__ __nv_bfloat16 g_wvh[CD * CD], g_wvl[CD * CD];
__device__ __nv_bfloat16 g_woh[CD * CD], g_wol[CD * CD];
__device__ __nv_bfloat16 g_qh[MROWS * CD], g_ql[MROWS * CD];     // projected Q split
__device__ __nv_bfloat16 g_kh[MROWS * CD], g_kl[MROWS * CD];     // projected K split
__device__ __nv_bfloat16 g_vh[MROWS * CD], g_vl[MROWS * CD];     // projected V split
__device__ __nv_bfloat16 g_ch[MROWS * CD], g_cl[MROWS * CD];     // context split

// ---------------------------------------------------------------------------
// PTX helpers (arch-agnostic: ldmatrix / mma.sync / cp.async)
// ---------------------------------------------------------------------------
__device__ __forceinline__ uint32_t smem_to_u32(const void* p) {
    uint32_t a;
    asm("{ .reg .u64 t; cvta.to.shared.u64 t, %1; cvt.u32.u64 %0, t; }"
        : "=r"(a) : "l"(p));
    return a;
}

__device__ __forceinline__ void cpasync16(uint32_t saddr, const void* gptr) {
    asm volatile("cp.async.cg.shared.global [%0], [%1], 16;"
                 :: "r"(saddr), "l"(__cvta_generic_to_global(gptr)));
}
#define CP_COMMIT()  asm volatile("cp.async.commit_group;")
#define CP_WAIT(n)   asm volatile("cp.async.wait_group %0;" :: "n"(n))

__device__ __forceinline__ void ldsm4(uint32_t* r, uint32_t addr) {
    asm volatile("ldmatrix.sync.aligned.m8n8.x4.shared.b16 {%0,%1,%2,%3}, [%4];"
                 : "=r"(r[0]), "=r"(r[1]), "=r"(r[2]), "=r"(r[3]) : "r"(addr));
}
__device__ __forceinline__ void ldsm4t(uint32_t* r, uint32_t addr) {
    asm volatile("ldmatrix.sync.aligned.m8n8.x4.trans.shared.b16 {%0,%1,%2,%3}, [%4];"
                 : "=r"(r[0]), "=r"(r[1]), "=r"(r[2]), "=r"(r[3]) : "r"(addr));
}
__device__ __forceinline__ void mma16816(float* c, const uint32_t* a,
                                         uint32_t b0, uint32_t b1) {
    asm volatile(
        "mma.sync.aligned.m16n8k16.row.col.f32.bf16.bf16.f32 "
        "{%0,%1,%2,%3}, {%4,%5,%6,%7}, {%8,%9}, {%0,%1,%2,%3};"
        : "+f"(c[0]), "+f"(c[1]), "+f"(c[2]), "+f"(c[3])
        : "r"(a[0]), "r"(a[1]), "r"(a[2]), "r"(a[3]), "r"(b0), "r"(b1));
}

// smem tile addressing: rows of 128 bytes (8 x 16B units), xor-swizzled
__device__ __forceinline__ uint32_t swofs(int row, int unit) {
    return (uint32_t)(row * 128 + ((unit ^ (row & 7)) << 4));
}

// split fp32 pair -> packed bf16x2 hi and lo
__device__ __forceinline__ void split2(float x, float y, uint32_t& hi, uint32_t& lo) {
    __nv_bfloat16 hx = __float2bfloat16(x), hy = __float2bfloat16(y);
    __nv_bfloat16 lx = __float2bfloat16(x - __bfloat162float(hx));
    __nv_bfloat16 ly = __float2bfloat16(y - __bfloat162float(hy));
    hi = (uint32_t)__bfloat16_as_ushort(hx) | ((uint32_t)__bfloat16_as_ushort(hy) << 16);
    lo = (uint32_t)__bfloat16_as_ushort(lx) | ((uint32_t)__bfloat16_as_ushort(ly) << 16);
}

// ---------------------------------------------------------------------------
// fp32 -> bf16 hi/lo split kernel
// ---------------------------------------------------------------------------
__global__ __launch_bounds__(256) void split_kernel(
    const float* __restrict__ x, __nv_bfloat16* __restrict__ hi,
    __nv_bfloat16* __restrict__ lo, int n4)
{
    int i = blockIdx.x * blockDim.x + threadIdx.x;
    if (i >= n4) return;
    float4 v = reinterpret_cast<const float4*>(x)[i];
    uint32_t h0, l0, h1, l1;
    split2(v.x, v.y, h0, l0);
    split2(v.z, v.w, h1, l1);
    reinterpret_cast<uint2*>(hi)[i] = make_uint2(h0, h1);
    reinterpret_cast<uint2*>(lo)[i] = make_uint2(l0, l1);
}

// ---------------------------------------------------------------------------
// HMMA GEMM: C[m][n] = sum_k A[m][k]*W[n][k] + bias[n]
// A = Ah+Al, W = Wh+Wl; 3 products via virtual K = 3*1024.
// BM=BN=128, BK=64; 256 threads (8 warps: 4M x 2N); 3-stage cp.async pipeline.
// SPLIT=true: write bf16 hi/lo outputs; else fp32.
// ---------------------------------------------------------------------------
constexpr int GSTAGE_B = 2 * 128 * 128;       // A tile 16KB + B tile 16KB
constexpr int GSMEM = 3 * GSTAGE_B;           // 96KB
constexpr int GNCH = 48;                      // 3 segments x 16 chunks of 64

template<bool SPLIT>
__global__ __launch_bounds__(256) void gemm_mma(
    const __nv_bfloat16* __restrict__ Ah, const __nv_bfloat16* __restrict__ Al,
    const __nv_bfloat16* __restrict__ Wh, const __nv_bfloat16* __restrict__ Wl,
    const float* __restrict__ bias,
    float* __restrict__ Cf, __nv_bfloat16* __restrict__ Ch,
    __nv_bfloat16* __restrict__ Cl)
{
    extern __shared__ char smem[];
    const uint32_t sbase = smem_to_u32(smem);
    const int tid = threadIdx.x, lane = tid & 31, wid = tid >> 5;
    const int m0 = blockIdx.y * 128, n0 = blockIdx.x * 128;
    const int mw = (wid & 3) * 32, nw = (wid >> 2) * 64;

    const __nv_bfloat16* aseg[3] = {Ah, Ah, Al};
    const __nv_bfloat16* bseg[3] = {Wh, Wl, Wh};

    float acc[2][8][4];
    #pragma unroll
    for (int mm = 0; mm < 2; mm++)
        #pragma unroll
        for (int nt = 0; nt < 8; nt++)
            #pragma unroll
            for (int c = 0; c < 4; c++) acc[mm][nt][c] = 0.0f;

    auto issue = [&](int kc) {
        int seg = kc >> 4, k0 = (kc & 15) * 64;
        const __nv_bfloat16* at = aseg[seg] + (size_t)m0 * CD + k0;
        const __nv_bfloat16* bt = bseg[seg] + (size_t)n0 * CD + k0;
        uint32_t st = sbase + (uint32_t)(kc % 3) * GSTAGE_B;
        #pragma unroll
        for (int j = 0; j < 4; ++j) {
            int idx = tid + j * 256, r = idx >> 3, u = idx & 7;
            cpasync16(st + swofs(r, u), at + (size_t)r * CD + u * 8);
        }
        uint32_t stb = st + 128 * 128;
        #pragma unroll
        for (int j = 0; j < 4; ++j) {
            int idx = tid + j * 256, r = idx >> 3, u = idx & 7;
            cpasync16(stb + swofs(r, u), bt + (size_t)r * CD + u * 8);
        }
        CP_COMMIT();
    };

    issue(0);
    issue(1);

    for (int kc = 0; kc < GNCH; ++kc) {
        if (kc + 2 < GNCH) { issue(kc + 2); CP_WAIT(2); }
        else if (kc + 1 < GNCH) { CP_WAIT(1); }
        else { CP_WAIT(0); }
        __syncthreads();

        uint32_t sa = sbase + (uint32_t)(kc % 3) * GSTAGE_B;
        uint32_t sb = sa + 128 * 128;
        #pragma unroll
        for (int ks = 0; ks < 4; ++ks) {
            uint32_t afr[2][4];
            #pragma unroll
            for (int mm = 0; mm < 2; ++mm) {
                int r = mw + mm * 16 + (lane & 15);
                int u = ks * 2 + (lane >> 4);
                ldsm4(afr[mm], sa + swofs(r, u));
            }
            #pragma unroll
            for (int bn = 0; bn < 4; ++bn) {
                int r = nw + bn * 16 + (lane & 7) + ((lane >> 4) << 3);
                int u = ks * 2 + ((lane >> 3) & 1);
                uint32_t bfr[4];
                ldsm4(bfr, sb + swofs(r, u));
                #pragma unroll
                for (int mm = 0; mm < 2; ++mm) {
                    mma16816(acc[mm][2 * bn],     afr[mm], bfr[0], bfr[1]);
                    mma16816(acc[mm][2 * bn + 1], afr[mm], bfr[2], bfr[3]);
                }
            }
        }
        __syncthreads();
    }

    // Epilogue
    const int g = lane >> 2, t = lane & 3;
    #pragma unroll
    for (int mm = 0; mm < 2; ++mm) {
        int row0 = m0 + mw + mm * 16 + g;
        #pragma unroll
        for (int nt = 0; nt < 8; ++nt) {
            int col = n0 + nw + nt * 8 + t * 2;
            float b0 = bias[col], b1 = bias[col + 1];
            float v00 = acc[mm][nt][0] + b0, v01 = acc[mm][nt][1] + b1;
            float v10 = acc[mm][nt][2] + b0, v11 = acc[mm][nt][3] + b1;
            if (SPLIT) {
                uint32_t h2, l2;
                split2(v00, v01, h2, l2);
                *reinterpret_cast<uint32_t*>(&Ch[(size_t)row0 * CD + col]) = h2;
                *reinterpret_cast<uint32_t*>(&Cl[(size_t)row0 * CD + col]) = l2;
                split2(v10, v11, h2, l2);
                *reinterpret_cast<uint32_t*>(&Ch[(size_t)(row0 + 8) * CD + col]) = h2;
                *reinterpret_cast<uint32_t*>(&Cl[(size_t)(row0 + 8) * CD + col]) = l2;
            } else {
                *reinterpret_cast<float2*>(&Cf[(size_t)row0 * CD + col]) =
                    make_float2(v00, v01);
                *reinterpret_cast<float2*>(&Cf[(size_t)(row0 + 8) * CD + col]) =
                    make_float2(v10, v11);
            }
        }
    }
}

// ---------------------------------------------------------------------------
// HMMA flash attention.
// Grid (16 q-tiles, 64 bh). 256 threads = 8 warps, warp w owns q rows w*16..+15.
// kt chunks of 64. S = Qh*Kh + Qh*Kl + Ql*Kh (split); online softmax in
// fragment layout; P split in registers -> PV = Ph*Vh + Ph*Vl + Pl*Vh.
// smem: Qh/Ql 2x16KB + 2 stages x (Kh,Kl,Vh,Vl 4x8KB) = 96KB.
// ---------------------------------------------------------------------------
constexpr int ASMEM = 32768 + 2 * 32768;   // 98304

__global__ __launch_bounds__(256) void attn_mma(
    const __nv_bfloat16* __restrict__ Qh, const __nv_bfloat16* __restrict__ Ql,
    const __nv_bfloat16* __restrict__ Kh, const __nv_bfloat16* __restrict__ Kl,
    const __nv_bfloat16* __restrict__ Vh, const __nv_bfloat16* __restrict__ Vl,
    __nv_bfloat16* __restrict__ Ch, __nv_bfloat16* __restrict__ Cl)
{
    extern __shared__ char smem[];
    const uint32_t sb = smem_to_u32(smem);
    const uint32_t smQh = sb, smQl = sb + 16384;
    const int tid = threadIdx.x, lane = tid & 31, wid = tid >> 5;
    const int q0 = blockIdx.x * 128;
    const int b = blockIdx.y >> 4, h = blockIdx.y & 15;
    const size_t tbase = (size_t)b * CS * CD + (size_t)h * CE;

    const __nv_bfloat16* qht = Qh + tbase + (size_t)q0 * CD;
    const __nv_bfloat16* qlt = Ql + tbase + (size_t)q0 * CD;

    auto issueKV = [&](int kc) {
        int kt0 = kc * 64;
        uint32_t st = sb + 32768 + (uint32_t)(kc & 1) * 32768;
        const __nv_bfloat16* srcs[4] = {Kh, Kl, Vh, Vl};
        #pragma unroll
        for (int m = 0; m < 4; ++m) {
            const __nv_bfloat16* p = srcs[m] + tbase + (size_t)kt0 * CD;
            #pragma unroll
            for (int j = 0; j < 2; ++j) {
                int idx = tid + j * 256, r = idx >> 3, u = idx & 7;
                cpasync16(st + m * 8192 + swofs(r, u), p + (size_t)r * CD + u * 8);
            }
        }
        CP_COMMIT();
    };

    // Q load + chunk 0 (one group)
    #pragma unroll
    for (int j = 0; j < 4; ++j) {
        int idx = tid + j * 256, r = idx >> 3, u = idx & 7;
        cpasync16(smQh + swofs(r, u), qht + (size_t)r * CD + u * 8);
        cpasync16(smQl + swofs(r, u), qlt + (size_t)r * CD + u * 8);
    }
    issueKV(0);

    float oacc[8][4];
    #pragma unroll
    for (int j = 0; j < 8; j++)
        #pragma unroll
        for (int c = 0; c < 4; c++) oacc[j][c] = 0.0f;
    float m0r = -1e30f, m1r = -1e30f, l0r = 0.0f, l1r = 0.0f;

    for (int kc = 0; kc < 32; ++kc) {
        if (kc + 1 < 32) { issueKV(kc + 1); CP_WAIT(1); }
        else { CP_WAIT(0); }
        __syncthreads();

        uint32_t st = sb + 32768 + (uint32_t)(kc & 1) * 32768;
        uint32_t stK[2] = {st, st + 8192};            // Kh, Kl
        uint32_t stVh = st + 16384, stVl = st + 24576;

        // ---- S = Q K^T (3 split products) ----
        float sacc[8][4];
        #pragma unroll
        for (int j = 0; j < 8; j++)
            #pragma unroll
            for (int c = 0; c < 4; c++) sacc[j][c] = 0.0f;

        #pragma unroll
        for (int seg = 0; seg < 3; ++seg) {
            uint32_t qb = (seg < 2) ? smQh : smQl;
            uint32_t kb = stK[(seg == 1) ? 1 : 0];
            #pragma unroll
            for (int ks = 0; ks < 4; ++ks) {
                uint32_t afr[4];
                int ar = wid * 16 + (lane & 15);
                int au = ks * 2 + (lane >> 4);
                ldsm4(afr, qb + swofs(ar, au));
                #pragma unroll
                for (int bn = 0; bn < 4; ++bn) {
                    int br = bn * 16 + (lane & 7) + ((lane >> 4) << 3);
                    int bu = ks * 2 + ((lane >> 3) & 1);
                    uint32_t bfr[4];
                    ldsm4(bfr, kb + swofs(br, bu));
                    mma16816(sacc[2 * bn],     afr, bfr[0], bfr[1]);
                    mma16816(sacc[2 * bn + 1], afr, bfr[2], bfr[3]);
                }
            }
        }
        #pragma unroll
        for (int j = 0; j < 8; j++)
            #pragma unroll
            for (int c = 0; c < 4; c++) sacc[j][c] *= 0.125f;

        // ---- online softmax (rows g and g+8 per lane) ----
        float mx0 = -1e30f, mx1 = -1e30f;
        #pragma unroll
        for (int j = 0; j < 8; j++) {
            mx0 = fmaxf(mx0, fmaxf(sacc[j][0], sacc[j][1]));
            mx1 = fmaxf(mx1, fmaxf(sacc[j][2], sacc[j][3]));
        }
        mx0 = fmaxf(mx0, __shfl_xor_sync(0xffffffffu, mx0, 1));
        mx0 = fmaxf(mx0, __shfl_xor_sync(0xffffffffu, mx0, 2));
        mx1 = fmaxf(mx1, __shfl_xor_sync(0xffffffffu, mx1, 1));
        mx1 = fmaxf(mx1, __shfl_xor_sync(0xffffffffu, mx1, 2));

        float mn0 = fmaxf(m0r, mx0), mn1 = fmaxf(m1r, mx1);
        float a0 = __expf(m0r - mn0), a1 = __expf(m1r - mn1);
        float s0 = 0.0f, s1 = 0.0f;
        #pragma unroll
        for (int j = 0; j < 8; j++) {
            sacc[j][0] = __expf(sacc[j][0] - mn0);
            sacc[j][1] = __expf(sacc[j][1] - mn0);
            sacc[j][2] = __expf(sacc[j][2] - mn1);
            sacc[j][3] = __expf(sacc[j][3] - mn1);
            s0 += sacc[j][0] + sacc[j][1];
            s1 += sacc[j][2] + sacc[j][3];
        }
        s0 += __shfl_xor_sync(0xffffffffu, s0, 1);
        s0 += __shfl_xor_sync(0xffffffffu, s0, 2);
        s1 += __shfl_xor_sync(0xffffffffu, s1, 1);
        s1 += __shfl_xor_sync(0xffffffffu, s1, 2);
        l0r = l0r * a0 + s0;
        l1r = l1r * a1 + s1;
        m0r = mn0; m1r = mn1;
        #pragma unroll
        for (int j = 0; j < 8; j++) {
            oacc[j][0] *= a0; oacc[j][1] *= a0;
            oacc[j][2] *= a1; oacc[j][3] *= a1;
        }

        // ---- O += P V (3 split products) ----
        #pragma unroll
        for (int kj = 0; kj < 4; ++kj) {
            uint32_t ph[4], pl[4];
            split2(sacc[2 * kj][0],     sacc[2 * kj][1],     ph[0], pl[0]);
            split2(sacc[2 * kj][2],     sacc[2 * kj][3],     ph[1], pl[1]);
            split2(sacc[2 * kj + 1][0], sacc[2 * kj + 1][1], ph[2], pl[2]);
            split2(sacc[2 * kj + 1][2], sacc[2 * kj + 1][3], ph[3], pl[3]);
            #pragma unroll
            for (int en = 0; en < 4; ++en) {
                int vr = kj * 16 + (lane & 7) + (((lane >> 3) & 1) << 3);
                int vu = en * 2 + (lane >> 4);
                uint32_t off = swofs(vr, vu);
                uint32_t vh4[4], vl4[4];
                ldsm4t(vh4, stVh + off);
                ldsm4t(vl4, stVl + off);
                mma16816(oacc[2 * en],     ph, vh4[0], vh4[1]);
                mma16816(oacc[2 * en + 1], ph, vh4[2], vh4[3]);
                mma16816(oacc[2 * en],     ph, vl4[0], vl4[1]);
                mma16816(oacc[2 * en + 1], ph, vl4[2], vl4[3]);
                mma16816(oacc[2 * en],     pl, vh4[0], vh4[1]);
                mma16816(oacc[2 * en + 1], pl, vh4[2], vh4[3]);
            }
        }
        __syncthreads();
    }

    // ---- epilogue: normalize, split to bf16 hi/lo, store ----
    const float inv0 = 1.0f / l0r, inv1 = 1.0f / l1r;
    const int g = lane >> 2, t = lane & 3;
    const int row0 = q0 + wid * 16 + g;
    #pragma unroll
    for (int nt = 0; nt < 8; ++nt) {
        int col = nt * 8 + t * 2;
        uint32_t h2, l2;
        split2(oacc[nt][0] * inv0, oacc[nt][1] * inv0, h2, l2);
        *reinterpret_cast<uint32_t*>(&Ch[tbase + (size_t)row0 * CD + col]) = h2;
        *reinterpret_cast<uint32_t*>(&Cl[tbase + (size_t)row0 * CD + col]) = l2;
        split2(oacc[nt][2] * inv1, oacc[nt][3] * inv1, h2, l2);
        *reinterpret_cast<uint32_t*>(&Ch[tbase + (size_t)(row0 + 8) * CD + col]) = h2;
        *reinterpret_cast<uint32_t*>(&Cl[tbase + (size_t)(row0 + 8) * CD + col]) = l2;
    }
}

// ---------------------------------------------------------------------------
// Launch
// ---------------------------------------------------------------------------
extern "C" void kernel_launch(void* const* d_in, const int* in_sizes, int n_in,
                              void* d_out, int out_size)
{
    const float* query = (const float*)d_in[0];
    const float* key   = (const float*)d_in[1];
    const float* value = (const float*)d_in[2];
    const float* wq    = (const float*)d_in[3];
    const float* bq    = (const float*)d_in[4];
    const float* wk    = (const float*)d_in[5];
    const float* bk    = (const float*)d_in[6];
    const float* wv    = (const float*)d_in[7];
    const float* bv    = (const float*)d_in[8];
    const float* wo    = (const float*)d_in[9];
    const float* bo    = (const float*)d_in[10];
    float* out = (float*)d_out;

    __nv_bfloat16 *xqh,*xql,*xkh,*xkl,*xvh,*xvl;
    __nv_bfloat16 *wqh,*wql,*wkh,*wkl,*wvh,*wvl,*woh,*wol;
    __nv_bfloat16 *qh,*ql,*kh,*kl,*vh,*vl,*ch,*cl;
    cudaGetSymbolAddress((void**)&xqh, g_xqh); cudaGetSymbolAddress((void**)&xql, g_xql);
    cudaGetSymbolAddress((void**)&xkh, g_xkh); cudaGetSymbolAddress((void**)&xkl, g_xkl);
    cudaGetSymbolAddress((void**)&xvh, g_xvh); cudaGetSymbolAddress((void**)&xvl, g_xvl);
    cudaGetSymbolAddress((void**)&wqh, g_wqh); cudaGetSymbolAddress((void**)&wql, g_wql);
    cudaGetSymbolAddress((void**)&wkh, g_wkh); cudaGetSymbolAddress((void**)&wkl, g_wkl);
    cudaGetSymbolAddress((void**)&wvh, g_wvh); cudaGetSymbolAddress((void**)&wvl, g_wvl);
    cudaGetSymbolAddress((void**)&woh, g_woh); cudaGetSymbolAddress((void**)&wol, g_wol);
    cudaGetSymbolAddress((void**)&qh, g_qh);   cudaGetSymbolAddress((void**)&ql, g_ql);
    cudaGetSymbolAddress((void**)&kh, g_kh);   cudaGetSymbolAddress((void**)&kl, g_kl);
    cudaGetSymbolAddress((void**)&vh, g_vh);   cudaGetSymbolAddress((void**)&vl, g_vl);
    cudaGetSymbolAddress((void**)&ch, g_ch);   cudaGetSymbolAddress((void**)&cl, g_cl);

    cudaFuncSetAttribute(gemm_mma<true>,
                         cudaFuncAttributeMaxDynamicSharedMemorySize, GSMEM);
    cudaFuncSetAttribute(gemm_mma<false>,
                         cudaFuncAttributeMaxDynamicSharedMemorySize, GSMEM);
    cudaFuncSetAttribute(attn_mma,
                         cudaFuncAttributeMaxDynamicSharedMemorySize, ASMEM);

    const int nBig = MROWS * CD / 4;   // 2M float4
    const int nW   = CD * CD / 4;      // 256K float4

    // Input + weight splits
    split_kernel<<<nBig / 256, 256>>>(query, xqh, xql, nBig);
    split_kernel<<<nBig / 256, 256>>>(key,   xkh, xkl, nBig);
    split_kernel<<<nBig / 256, 256>>>(value, xvh, xvl, nBig);
    split_kernel<<<nW / 256, 256>>>(wq, wqh, wql, nW);
    split_kernel<<<nW / 256, 256>>>(wk, wkh, wkl, nW);
    split_kernel<<<nW / 256, 256>>>(wv, wvh, wvl, nW);
    split_kernel<<<nW / 256, 256>>>(wo, woh, wol, nW);

    dim3 ggrid(CD / 128, MROWS / 128);  // (8, 64)
    // Projections -> bf16 hi/lo
    gemm_mma<true><<<ggrid, 256, GSMEM>>>(xqh, xql, wqh, wql, bq, nullptr, qh, ql);
    gemm_mma<true><<<ggrid, 256, GSMEM>>>(xkh, xkl, wkh, wkl, bk, nullptr, kh, kl);
    gemm_mma<true><<<ggrid, 256, GSMEM>>>(xvh, xvl, wvh, wvl, bv, nullptr, vh, vl);

    // Attention -> ctx bf16 hi/lo
    attn_mma<<<dim3(CS / 128, CB * CH), 256, ASMEM>>>(qh, ql, kh, kl, vh, vl, ch, cl);

    // Output projection -> fp32 out
    gemm_mma<false><<<ggrid, 256, GSMEM>>>(ch, cl, woh, wol, bo, out, nullptr, nullptr);
}

// round 4
// speedup vs baseline: 3.8434x; 1.3754x over previous
#include <cuda_runtime.h>
#include <cuda_bf16.h>
#include <cuda_fp16.h>
#include <cstdint>

// ---------------------------------------------------------------------------
// Problem constants (B=4, S=2048, D=1024, H=16, DQKV=64)
// ---------------------------------------------------------------------------
constexpr int CB = 4;
constexpr int CS = 2048;
constexpr int CD = 1024;
constexpr int CH = 16;
constexpr int CE = 64;
constexpr int MROWS = CB * CS;   // 8192

// ---------------------------------------------------------------------------
// Device scratch (allocation-free)
// ---------------------------------------------------------------------------
__device__ __nv_bfloat16 g_xqh[MROWS * CD], g_xql[MROWS * CD];
__device__ __nv_bfloat16 g_xkh[MROWS * CD], g_xkl[MROWS * CD];
__device__ __nv_bfloat16 g_xvh[MROWS * CD], g_xvl[MROWS * CD];
__device__ __nv_bfloat16 g_wqh[CD * CD], g_wql[CD * CD];
__device__ __nv_bfloat16 g_wkh[CD * CD], g_wkl[CD * CD];
__device__ __nv_bfloat16 g_wvh[CD * CD], g_wvl[CD * CD];
__device__ __nv_bfloat16 g_woh[CD * CD], g_wol[CD * CD];
__device__ __half g_qf[MROWS * CD];       // projected Q (fp16)
__device__ __half g_kf[MROWS * CD];       // projected K (fp16)
__device__ __half g_vf[MROWS * CD];       // projected V (fp16)
__device__ __nv_bfloat16 g_ch[MROWS * CD], g_cl[MROWS * CD];   // context split

// ---------------------------------------------------------------------------
// PTX helpers (arch-agnostic: ldmatrix / mma.sync / cp.async)
// ---------------------------------------------------------------------------
__device__ __forceinline__ uint32_t smem_to_u32(const void* p) {
    uint32_t a;
    asm("{ .reg .u64 t; cvta.to.shared.u64 t, %1; cvt.u32.u64 %0, t; }"
        : "=r"(a) : "l"(p));
    return a;
}

__device__ __forceinline__ void cpasync16(uint32_t saddr, const void* gptr) {
    asm volatile("cp.async.cg.shared.global [%0], [%1], 16;"
                 :: "r"(saddr), "l"(__cvta_generic_to_global(gptr)));
}
#define CP_COMMIT()  asm volatile("cp.async.commit_group;")
#define CP_WAIT(n)   asm volatile("cp.async.wait_group %0;" :: "n"(n))

__device__ __forceinline__ void ldsm4(uint32_t* r, uint32_t addr) {
    asm volatile("ldmatrix.sync.aligned.m8n8.x4.shared.b16 {%0,%1,%2,%3}, [%4];"
                 : "=r"(r[0]), "=r"(r[1]), "=r"(r[2]), "=r"(r[3]) : "r"(addr));
}
__device__ __forceinline__ void ldsm4t(uint32_t* r, uint32_t addr) {
    asm volatile("ldmatrix.sync.aligned.m8n8.x4.trans.shared.b16 {%0,%1,%2,%3}, [%4];"
                 : "=r"(r[0]), "=r"(r[1]), "=r"(r[2]), "=r"(r[3]) : "r"(addr));
}
__device__ __forceinline__ void mma16816(float* c, const uint32_t* a,
                                         uint32_t b0, uint32_t b1) {
    asm volatile(
        "mma.sync.aligned.m16n8k16.row.col.f32.bf16.bf16.f32 "
        "{%0,%1,%2,%3}, {%4,%5,%6,%7}, {%8,%9}, {%0,%1,%2,%3};"
        : "+f"(c[0]), "+f"(c[1]), "+f"(c[2]), "+f"(c[3])
        : "r"(a[0]), "r"(a[1]), "r"(a[2]), "r"(a[3]), "r"(b0), "r"(b1));
}
__device__ __forceinline__ void mma16816h(float* c, const uint32_t* a,
                                          uint32_t b0, uint32_t b1) {
    asm volatile(
        "mma.sync.aligned.m16n8k16.row.col.f32.f16.f16.f32 "
        "{%0,%1,%2,%3}, {%4,%5,%6,%7}, {%8,%9}, {%0,%1,%2,%3};"
        : "+f"(c[0]), "+f"(c[1]), "+f"(c[2]), "+f"(c[3])
        : "r"(a[0]), "r"(a[1]), "r"(a[2]), "r"(a[3]), "r"(b0), "r"(b1));
}

// smem tile addressing: rows of 128 bytes (8 x 16B units), xor-swizzled
__device__ __forceinline__ uint32_t swofs(int row, int unit) {
    return (uint32_t)(row * 128 + ((unit ^ (row & 7)) << 4));
}

// split fp32 pair -> packed bf16x2 hi and lo
__device__ __forceinline__ void split2(float x, float y, uint32_t& hi, uint32_t& lo) {
    __nv_bfloat16 hx = __float2bfloat16(x), hy = __float2bfloat16(y);
    __nv_bfloat16 lx = __float2bfloat16(x - __bfloat162float(hx));
    __nv_bfloat16 ly = __float2bfloat16(y - __bfloat162float(hy));
    hi = (uint32_t)__bfloat16_as_ushort(hx) | ((uint32_t)__bfloat16_as_ushort(hy) << 16);
    lo = (uint32_t)__bfloat16_as_ushort(lx) | ((uint32_t)__bfloat16_as_ushort(ly) << 16);
}

__device__ __forceinline__ uint32_t pack_f16(float x, float y) {
    __half2 h = __floats2half2_rn(x, y);
    return *reinterpret_cast<uint32_t*>(&h);
}

// ---------------------------------------------------------------------------
// fp32 -> bf16 hi/lo split kernel
// ---------------------------------------------------------------------------
__global__ __launch_bounds__(256) void split_kernel(
    const float* __restrict__ x, __nv_bfloat16* __restrict__ hi,
    __nv_bfloat16* __restrict__ lo, int n4)
{
    int i = blockIdx.x * blockDim.x + threadIdx.x;
    if (i >= n4) return;
    float4 v = reinterpret_cast<const float4*>(x)[i];
    uint32_t h0, l0, h1, l1;
    split2(v.x, v.y, h0, l0);
    split2(v.z, v.w, h1, l1);
    reinterpret_cast<uint2*>(hi)[i] = make_uint2(h0, h1);
    reinterpret_cast<uint2*>(lo)[i] = make_uint2(l0, l1);
}

// ---------------------------------------------------------------------------
// HMMA GEMM (bf16 3-product split): C = A*W^T + bias
// OMODE 0: fp32 out; OMODE 1: fp16 out.
// BM=BN=128, BK=64; 256 threads (8 warps: 4M x 2N); 3-stage cp.async pipeline.
// ---------------------------------------------------------------------------
constexpr int GSTAGE_B = 2 * 128 * 128;
constexpr int GSMEM = 3 * GSTAGE_B;           // 96KB
constexpr int GNCH = 48;

template<int OMODE>
__global__ __launch_bounds__(256) void gemm_mma(
    const __nv_bfloat16* __restrict__ Ah, const __nv_bfloat16* __restrict__ Al,
    const __nv_bfloat16* __restrict__ Wh, const __nv_bfloat16* __restrict__ Wl,
    const float* __restrict__ bias,
    float* __restrict__ Cf, __half* __restrict__ Cg)
{
    extern __shared__ char smem[];
    const uint32_t sbase = smem_to_u32(smem);
    const int tid = threadIdx.x, lane = tid & 31, wid = tid >> 5;
    const int m0 = blockIdx.y * 128, n0 = blockIdx.x * 128;
    const int mw = (wid & 3) * 32, nw = (wid >> 2) * 64;

    const __nv_bfloat16* aseg[3] = {Ah, Ah, Al};
    const __nv_bfloat16* bseg[3] = {Wh, Wl, Wh};

    float acc[2][8][4];
    #pragma unroll
    for (int mm = 0; mm < 2; mm++)
        #pragma unroll
        for (int nt = 0; nt < 8; nt++)
            #pragma unroll
            for (int c = 0; c < 4; c++) acc[mm][nt][c] = 0.0f;

    auto issue = [&](int kc) {
        int seg = kc >> 4, k0 = (kc & 15) * 64;
        const __nv_bfloat16* at = aseg[seg] + (size_t)m0 * CD + k0;
        const __nv_bfloat16* bt = bseg[seg] + (size_t)n0 * CD + k0;
        uint32_t st = sbase + (uint32_t)(kc % 3) * GSTAGE_B;
        #pragma unroll
        for (int j = 0; j < 4; ++j) {
            int idx = tid + j * 256, r = idx >> 3, u = idx & 7;
            cpasync16(st + swofs(r, u), at + (size_t)r * CD + u * 8);
        }
        uint32_t stb = st + 128 * 128;
        #pragma unroll
        for (int j = 0; j < 4; ++j) {
            int idx = tid + j * 256, r = idx >> 3, u = idx & 7;
            cpasync16(stb + swofs(r, u), bt + (size_t)r * CD + u * 8);
        }
        CP_COMMIT();
    };

    issue(0);
    issue(1);

    for (int kc = 0; kc < GNCH; ++kc) {
        if (kc + 2 < GNCH) { issue(kc + 2); CP_WAIT(2); }
        else if (kc + 1 < GNCH) { CP_WAIT(1); }
        else { CP_WAIT(0); }
        __syncthreads();

        uint32_t sa = sbase + (uint32_t)(kc % 3) * GSTAGE_B;
        uint32_t sb = sa + 128 * 128;
        #pragma unroll
        for (int ks = 0; ks < 4; ++ks) {
            uint32_t afr[2][4];
            #pragma unroll
            for (int mm = 0; mm < 2; ++mm) {
                int r = mw + mm * 16 + (lane & 15);
                int u = ks * 2 + (lane >> 4);
                ldsm4(afr[mm], sa + swofs(r, u));
            }
            #pragma unroll
            for (int bn = 0; bn < 4; ++bn) {
                int r = nw + bn * 16 + (lane & 7) + ((lane >> 4) << 3);
                int u = ks * 2 + ((lane >> 3) & 1);
                uint32_t bfr[4];
                ldsm4(bfr, sb + swofs(r, u));
                #pragma unroll
                for (int mm = 0; mm < 2; ++mm) {
                    mma16816(acc[mm][2 * bn],     afr[mm], bfr[0], bfr[1]);
                    mma16816(acc[mm][2 * bn + 1], afr[mm], bfr[2], bfr[3]);
                }
            }
        }
        __syncthreads();
    }

    const int g = lane >> 2, t = lane & 3;
    #pragma unroll
    for (int mm = 0; mm < 2; ++mm) {
        int row0 = m0 + mw + mm * 16 + g;
        #pragma unroll
        for (int nt = 0; nt < 8; ++nt) {
            int col = n0 + nw + nt * 8 + t * 2;
            float b0 = bias[col], b1 = bias[col + 1];
            float v00 = acc[mm][nt][0] + b0, v01 = acc[mm][nt][1] + b1;
            float v10 = acc[mm][nt][2] + b0, v11 = acc[mm][nt][3] + b1;
            if (OMODE == 1) {
                *reinterpret_cast<uint32_t*>(&Cg[(size_t)row0 * CD + col]) =
                    pack_f16(v00, v01);
                *reinterpret_cast<uint32_t*>(&Cg[(size_t)(row0 + 8) * CD + col]) =
                    pack_f16(v10, v11);
            } else {
                *reinterpret_cast<float2*>(&Cf[(size_t)row0 * CD + col]) =
                    make_float2(v00, v01);
                *reinterpret_cast<float2*>(&Cf[(size_t)(row0 + 8) * CD + col]) =
                    make_float2(v10, v11);
            }
        }
    }
}

// ---------------------------------------------------------------------------
// fp16 HMMA flash attention (single product).
// Grid (16 q-tiles, 64 bh). 256 threads = 8 warps; warp w owns q rows w*16..+15.
// smem: Q 16KB + 2 stages x (K 8KB + V 8KB) = 48KB.
// Output: context as bf16 hi/lo (feeds 3-product output GEMM).
// ---------------------------------------------------------------------------
constexpr int ASMEM = 16384 + 2 * 16384;   // 49152

__global__ __launch_bounds__(256) void attn_f16(
    const __half* __restrict__ Qf, const __half* __restrict__ Kf,
    const __half* __restrict__ Vf,
    __nv_bfloat16* __restrict__ Ch, __nv_bfloat16* __restrict__ Cl)
{
    extern __shared__ char smem[];
    const uint32_t sb = smem_to_u32(smem);
    const uint32_t smQ = sb;
    const int tid = threadIdx.x, lane = tid & 31, wid = tid >> 5;
    const int q0 = blockIdx.x * 128;
    const int b = blockIdx.y >> 4, h = blockIdx.y & 15;
    const size_t tbase = (size_t)b * CS * CD + (size_t)h * CE;

    const __half* qt = Qf + tbase + (size_t)q0 * CD;

    auto issueKV = [&](int kc) {
        int kt0 = kc * 64;
        uint32_t st = sb + 16384 + (uint32_t)(kc & 1) * 16384;
        const __half* kp = Kf + tbase + (size_t)kt0 * CD;
        const __half* vp = Vf + tbase + (size_t)kt0 * CD;
        #pragma unroll
        for (int j = 0; j < 2; ++j) {
            int idx = tid + j * 256, r = idx >> 3, u = idx & 7;
            cpasync16(st + swofs(r, u), kp + (size_t)r * CD + u * 8);
            cpasync16(st + 8192 + swofs(r, u), vp + (size_t)r * CD + u * 8);
        }
        CP_COMMIT();
    };

    // Q load + chunk 0 (one group)
    #pragma unroll
    for (int j = 0; j < 4; ++j) {
        int idx = tid + j * 256, r = idx >> 3, u = idx & 7;
        cpasync16(smQ + swofs(r, u), qt + (size_t)r * CD + u * 8);
    }
    issueKV(0);

    float oacc[8][4];
    #pragma unroll
    for (int j = 0; j < 8; j++)
        #pragma unroll
        for (int c = 0; c < 4; c++) oacc[j][c] = 0.0f;
    float m0r = -1e30f, m1r = -1e30f, l0r = 0.0f, l1r = 0.0f;

    for (int kc = 0; kc < 32; ++kc) {
        if (kc + 1 < 32) { issueKV(kc + 1); CP_WAIT(1); }
        else { CP_WAIT(0); }
        __syncthreads();

        uint32_t st = sb + 16384 + (uint32_t)(kc & 1) * 16384;
        uint32_t stK = st, stV = st + 8192;

        // ---- S = Q K^T (single fp16 product) ----
        float sacc[8][4];
        #pragma unroll
        for (int j = 0; j < 8; j++)
            #pragma unroll
            for (int c = 0; c < 4; c++) sacc[j][c] = 0.0f;

        #pragma unroll
        for (int ks = 0; ks < 4; ++ks) {
            uint32_t afr[4];
            int ar = wid * 16 + (lane & 15);
            int au = ks * 2 + (lane >> 4);
            ldsm4(afr, smQ + swofs(ar, au));
            #pragma unroll
            for (int bn = 0; bn < 4; ++bn) {
                int br = bn * 16 + (lane & 7) + ((lane >> 4) << 3);
                int bu = ks * 2 + ((lane >> 3) & 1);
                uint32_t bfr[4];
                ldsm4(bfr, stK + swofs(br, bu));
                mma16816h(sacc[2 * bn],     afr, bfr[0], bfr[1]);
                mma16816h(sacc[2 * bn + 1], afr, bfr[2], bfr[3]);
            }
        }
        #pragma unroll
        for (int j = 0; j < 8; j++)
            #pragma unroll
            for (int c = 0; c < 4; c++) sacc[j][c] *= 0.125f;

        // ---- online softmax (rows g and g+8 per lane) ----
        float mx0 = -1e30f, mx1 = -1e30f;
        #pragma unroll
        for (int j = 0; j < 8; j++) {
            mx0 = fmaxf(mx0, fmaxf(sacc[j][0], sacc[j][1]));
            mx1 = fmaxf(mx1, fmaxf(sacc[j][2], sacc[j][3]));
        }
        mx0 = fmaxf(mx0, __shfl_xor_sync(0xffffffffu, mx0, 1));
        mx0 = fmaxf(mx0, __shfl_xor_sync(0xffffffffu, mx0, 2));
        mx1 = fmaxf(mx1, __shfl_xor_sync(0xffffffffu, mx1, 1));
        mx1 = fmaxf(mx1, __shfl_xor_sync(0xffffffffu, mx1, 2));

        float mn0 = fmaxf(m0r, mx0), mn1 = fmaxf(m1r, mx1);
        float a0 = __expf(m0r - mn0), a1 = __expf(m1r - mn1);
        float s0 = 0.0f, s1 = 0.0f;
        #pragma unroll
        for (int j = 0; j < 8; j++) {
            sacc[j][0] = __expf(sacc[j][0] - mn0);
            sacc[j][1] = __expf(sacc[j][1] - mn0);
            sacc[j][2] = __expf(sacc[j][2] - mn1);
            sacc[j][3] = __expf(sacc[j][3] - mn1);
            s0 += sacc[j][0] + sacc[j][1];
            s1 += sacc[j][2] + sacc[j][3];
        }
        s0 += __shfl_xor_sync(0xffffffffu, s0, 1);
        s0 += __shfl_xor_sync(0xffffffffu, s0, 2);
        s1 += __shfl_xor_sync(0xffffffffu, s1, 1);
        s1 += __shfl_xor_sync(0xffffffffu, s1, 2);
        l0r = l0r * a0 + s0;
        l1r = l1r * a1 + s1;
        m0r = mn0; m1r = mn1;
        #pragma unroll
        for (int j = 0; j < 8; j++) {
            oacc[j][0] *= a0; oacc[j][1] *= a0;
            oacc[j][2] *= a1; oacc[j][3] *= a1;
        }

        // ---- O += P V (single fp16 product) ----
        #pragma unroll
        for (int kj = 0; kj < 4; ++kj) {
            uint32_t p[4];
            p[0] = pack_f16(sacc[2 * kj][0],     sacc[2 * kj][1]);
            p[1] = pack_f16(sacc[2 * kj][2],     sacc[2 * kj][3]);
            p[2] = pack_f16(sacc[2 * kj + 1][0], sacc[2 * kj + 1][1]);
            p[3] = pack_f16(sacc[2 * kj + 1][2], sacc[2 * kj + 1][3]);
            #pragma unroll
            for (int en = 0; en < 4; ++en) {
                int vr = kj * 16 + (lane & 7) + (((lane >> 3) & 1) << 3);
                int vu = en * 2 + (lane >> 4);
                uint32_t vfr[4];
                ldsm4t(vfr, stV + swofs(vr, vu));
                mma16816h(oacc[2 * en],     p, vfr[0], vfr[1]);
                mma16816h(oacc[2 * en + 1], p, vfr[2], vfr[3]);
            }
        }
        __syncthreads();
    }

    // ---- epilogue: normalize, split to bf16 hi/lo, store ----
    const float inv0 = 1.0f / l0r, inv1 = 1.0f / l1r;
    const int g = lane >> 2, t = lane & 3;
    const int row0 = q0 + wid * 16 + g;
    #pragma unroll
    for (int nt = 0; nt < 8; ++nt) {
        int col = nt * 8 + t * 2;
        uint32_t h2, l2;
        split2(oacc[nt][0] * inv0, oacc[nt][1] * inv0, h2, l2);
        *reinterpret_cast<uint32_t*>(&Ch[tbase + (size_t)row0 * CD + col]) = h2;
        *reinterpret_cast<uint32_t*>(&Cl[tbase + (size_t)row0 * CD + col]) = l2;
        split2(oacc[nt][2] * inv1, oacc[nt][3] * inv1, h2, l2);
        *reinterpret_cast<uint32_t*>(&Ch[tbase + (size_t)(row0 + 8) * CD + col]) = h2;
        *reinterpret_cast<uint32_t*>(&Cl[tbase + (size_t)(row0 + 8) * CD + col]) = l2;
    }
}

// ---------------------------------------------------------------------------
// Launch
// ---------------------------------------------------------------------------
extern "C" void kernel_launch(void* const* d_in, const int* in_sizes, int n_in,
                              void* d_out, int out_size)
{
    const float* query = (const float*)d_in[0];
    const float* key   = (const float*)d_in[1];
    const float* value = (const float*)d_in[2];
    const float* wq    = (const float*)d_in[3];
    const float* bq    = (const float*)d_in[4];
    const float* wk    = (const float*)d_in[5];
    const float* bk    = (const float*)d_in[6];
    const float* wv    = (const float*)d_in[7];
    const float* bv    = (const float*)d_in[8];
    const float* wo    = (const float*)d_in[9];
    const float* bo    = (const float*)d_in[10];
    float* out = (float*)d_out;

    __nv_bfloat16 *xqh,*xql,*xkh,*xkl,*xvh,*xvl;
    __nv_bfloat16 *wqh,*wql,*wkh,*wkl,*wvh,*wvl,*woh,*wol;
    __nv_bfloat16 *ch,*cl;
    __half *qf,*kf,*vf;
    cudaGetSymbolAddress((void**)&xqh, g_xqh); cudaGetSymbolAddress((void**)&xql, g_xql);
    cudaGetSymbolAddress((void**)&xkh, g_xkh); cudaGetSymbolAddress((void**)&xkl, g_xkl);
    cudaGetSymbolAddress((void**)&xvh, g_xvh); cudaGetSymbolAddress((void**)&xvl, g_xvl);
    cudaGetSymbolAddress((void**)&wqh, g_wqh); cudaGetSymbolAddress((void**)&wql, g_wql);
    cudaGetSymbolAddress((void**)&wkh, g_wkh); cudaGetSymbolAddress((void**)&wkl, g_wkl);
    cudaGetSymbolAddress((void**)&wvh, g_wvh); cudaGetSymbolAddress((void**)&wvl, g_wvl);
    cudaGetSymbolAddress((void**)&woh, g_woh); cudaGetSymbolAddress((void**)&wol, g_wol);
    cudaGetSymbolAddress((void**)&qf, g_qf);   cudaGetSymbolAddress((void**)&kf, g_kf);
    cudaGetSymbolAddress((void**)&vf, g_vf);
    cudaGetSymbolAddress((void**)&ch, g_ch);   cudaGetSymbolAddress((void**)&cl, g_cl);

    cudaFuncSetAttribute(gemm_mma<0>,
                         cudaFuncAttributeMaxDynamicSharedMemorySize, GSMEM);
    cudaFuncSetAttribute(gemm_mma<1>,
                         cudaFuncAttributeMaxDynamicSharedMemorySize, GSMEM);
    cudaFuncSetAttribute(attn_f16,
                         cudaFuncAttributeMaxDynamicSharedMemorySize, ASMEM);

    const int nBig = MROWS * CD / 4;
    const int nW   = CD * CD / 4;

    split_kernel<<<nBig / 256, 256>>>(query, xqh, xql, nBig);
    split_kernel<<<nBig / 256, 256>>>(key,   xkh, xkl, nBig);
    split_kernel<<<nBig / 256, 256>>>(value, xvh, xvl, nBig);
    split_kernel<<<nW / 256, 256>>>(wq, wqh, wql, nW);
    split_kernel<<<nW / 256, 256>>>(wk, wkh, wkl, nW);
    split_kernel<<<nW / 256, 256>>>(wv, wvh, wvl, nW);
    split_kernel<<<nW / 256, 256>>>(wo, woh, wol, nW);

    dim3 ggrid(CD / 128, MROWS / 128);  // (8, 64)
    // Projections -> fp16 Q/K/V (bf16 3-product internally)
    gemm_mma<1><<<ggrid, 256, GSMEM>>>(xqh, xql, wqh, wql, bq, nullptr, qf);
    gemm_mma<1><<<ggrid, 256, GSMEM>>>(xkh, xkl, wkh, wkl, bk, nullptr, kf);
    gemm_mma<1><<<ggrid, 256, GSMEM>>>(xvh, xvl, wvh, wvl, bv, nullptr, vf);

    // Attention (fp16 single product) -> ctx bf16 hi/lo
    attn_f16<<<dim3(CS / 128, CB * CH), 256, ASMEM>>>(qf, kf, vf, ch, cl);

    // Output projection -> fp32 out (bf16 3-product)
    gemm_mma<0><<<ggrid, 256, GSMEM>>>(ch, cl, woh, wol, bo, out, nullptr);
}

// round 5
// speedup vs baseline: 6.8556x; 1.7838x over previous
#include <cuda_runtime.h>
#include <cuda_fp16.h>
#include <cstdint>

// ---------------------------------------------------------------------------
// Problem constants (B=4, S=2048, D=1024, H=16, DQKV=64)
// ---------------------------------------------------------------------------
constexpr int CB = 4;
constexpr int CS = 2048;
constexpr int CD = 1024;
constexpr int CH = 16;
constexpr int CE = 64;
constexpr int MROWS = CB * CS;   // 8192

// ---------------------------------------------------------------------------
// Device scratch (allocation-free): everything fp16
// ---------------------------------------------------------------------------
__device__ __half g_xq[MROWS * CD], g_xk[MROWS * CD], g_xv[MROWS * CD];
__device__ __half g_wq16[CD * CD], g_wk16[CD * CD], g_wv16[CD * CD], g_wo16[CD * CD];
__device__ __half g_qf[MROWS * CD], g_kf[MROWS * CD], g_vf[MROWS * CD];
__device__ __half g_cf[MROWS * CD];

// ---------------------------------------------------------------------------
// PTX helpers (arch-agnostic: ldmatrix / mma.sync / cp.async)
// ---------------------------------------------------------------------------
__device__ __forceinline__ uint32_t smem_to_u32(const void* p) {
    uint32_t a;
    asm("{ .reg .u64 t; cvta.to.shared.u64 t, %1; cvt.u32.u64 %0, t; }"
        : "=r"(a) : "l"(p));
    return a;
}

__device__ __forceinline__ void cpasync16(uint32_t saddr, const void* gptr) {
    asm volatile("cp.async.cg.shared.global [%0], [%1], 16;"
                 :: "r"(saddr), "l"(__cvta_generic_to_global(gptr)));
}
#define CP_COMMIT()  asm volatile("cp.async.commit_group;")
#define CP_WAIT(n)   asm volatile("cp.async.wait_group %0;" :: "n"(n))

__device__ __forceinline__ void ldsm4(uint32_t* r, uint32_t addr) {
    asm volatile("ldmatrix.sync.aligned.m8n8.x4.shared.b16 {%0,%1,%2,%3}, [%4];"
                 : "=r"(r[0]), "=r"(r[1]), "=r"(r[2]), "=r"(r[3]) : "r"(addr));
}
__device__ __forceinline__ void ldsm4t(uint32_t* r, uint32_t addr) {
    asm volatile("ldmatrix.sync.aligned.m8n8.x4.trans.shared.b16 {%0,%1,%2,%3}, [%4];"
                 : "=r"(r[0]), "=r"(r[1]), "=r"(r[2]), "=r"(r[3]) : "r"(addr));
}
__device__ __forceinline__ void mma16816h(float* c, const uint32_t* a,
                                          uint32_t b0, uint32_t b1) {
    asm volatile(
        "mma.sync.aligned.m16n8k16.row.col.f32.f16.f16.f32 "
        "{%0,%1,%2,%3}, {%4,%5,%6,%7}, {%8,%9}, {%0,%1,%2,%3};"
        : "+f"(c[0]), "+f"(c[1]), "+f"(c[2]), "+f"(c[3])
        : "r"(a[0]), "r"(a[1]), "r"(a[2]), "r"(a[3]), "r"(b0), "r"(b1));
}

// smem tile addressing: rows of 128 bytes (8 x 16B units), xor-swizzled
__device__ __forceinline__ uint32_t swofs(int row, int unit) {
    return (uint32_t)(row * 128 + ((unit ^ (row & 7)) << 4));
}

__device__ __forceinline__ uint32_t pack_f16(float x, float y) {
    __half2 h = __floats2half2_rn(x, y);
    return *reinterpret_cast<uint32_t*>(&h);
}

// ---------------------------------------------------------------------------
// fp32 -> fp16 convert kernel
// ---------------------------------------------------------------------------
__global__ __launch_bounds__(256) void conv16_kernel(
    const float* __restrict__ x, __half* __restrict__ y, int n4)
{
    int i = blockIdx.x * blockDim.x + threadIdx.x;
    if (i >= n4) return;
    float4 v = reinterpret_cast<const float4*>(x)[i];
    reinterpret_cast<uint2*>(y)[i] =
        make_uint2(pack_f16(v.x, v.y), pack_f16(v.z, v.w));
}

// ---------------------------------------------------------------------------
// fp16 HMMA GEMM: C[m][n] = sum_k A[m][k]*W[n][k] + bias[n]
// BM=BN=128, BK=64; 256 threads (8 warps: 4M x 2N); 3-stage cp.async pipeline.
// OMODE 0: fp32 out; OMODE 1: fp16 out.
// ---------------------------------------------------------------------------
constexpr int GSTAGE_B = 2 * 128 * 128;       // A tile 16KB + B tile 16KB
constexpr int GSMEM = 3 * GSTAGE_B;           // 96KB
constexpr int GNCH = 16;                      // 16 chunks of K=64

template<int OMODE>
__global__ __launch_bounds__(256) void gemm_f16(
    const __half* __restrict__ A, const __half* __restrict__ W,
    const float* __restrict__ bias,
    float* __restrict__ Cf, __half* __restrict__ Cg)
{
    extern __shared__ char smem[];
    const uint32_t sbase = smem_to_u32(smem);
    const int tid = threadIdx.x, lane = tid & 31, wid = tid >> 5;
    const int m0 = blockIdx.y * 128, n0 = blockIdx.x * 128;
    const int mw = (wid & 3) * 32, nw = (wid >> 2) * 64;

    float acc[2][8][4];
    #pragma unroll
    for (int mm = 0; mm < 2; mm++)
        #pragma unroll
        for (int nt = 0; nt < 8; nt++)
            #pragma unroll
            for (int c = 0; c < 4; c++) acc[mm][nt][c] = 0.0f;

    auto issue = [&](int kc) {
        int k0 = kc * 64;
        const __half* at = A + (size_t)m0 * CD + k0;
        const __half* bt = W + (size_t)n0 * CD + k0;
        uint32_t st = sbase + (uint32_t)(kc % 3) * GSTAGE_B;
        #pragma unroll
        for (int j = 0; j < 4; ++j) {
            int idx = tid + j * 256, r = idx >> 3, u = idx & 7;
            cpasync16(st + swofs(r, u), at + (size_t)r * CD + u * 8);
        }
        uint32_t stb = st + 128 * 128;
        #pragma unroll
        for (int j = 0; j < 4; ++j) {
            int idx = tid + j * 256, r = idx >> 3, u = idx & 7;
            cpasync16(stb + swofs(r, u), bt + (size_t)r * CD + u * 8);
        }
        CP_COMMIT();
    };

    issue(0);
    issue(1);

    for (int kc = 0; kc < GNCH; ++kc) {
        if (kc + 2 < GNCH) { issue(kc + 2); CP_WAIT(2); }
        else if (kc + 1 < GNCH) { CP_WAIT(1); }
        else { CP_WAIT(0); }
        __syncthreads();

        uint32_t sa = sbase + (uint32_t)(kc % 3) * GSTAGE_B;
        uint32_t sb = sa + 128 * 128;
        #pragma unroll
        for (int ks = 0; ks < 4; ++ks) {
            uint32_t afr[2][4];
            #pragma unroll
            for (int mm = 0; mm < 2; ++mm) {
                int r = mw + mm * 16 + (lane & 15);
                int u = ks * 2 + (lane >> 4);
                ldsm4(afr[mm], sa + swofs(r, u));
            }
            #pragma unroll
            for (int bn = 0; bn < 4; ++bn) {
                int r = nw + bn * 16 + (lane & 7) + ((lane >> 4) << 3);
                int u = ks * 2 + ((lane >> 3) & 1);
                uint32_t bfr[4];
                ldsm4(bfr, sb + swofs(r, u));
                #pragma unroll
                for (int mm = 0; mm < 2; ++mm) {
                    mma16816h(acc[mm][2 * bn],     afr[mm], bfr[0], bfr[1]);
                    mma16816h(acc[mm][2 * bn + 1], afr[mm], bfr[2], bfr[3]);
                }
            }
        }
        __syncthreads();
    }

    const int g = lane >> 2, t = lane & 3;
    #pragma unroll
    for (int mm = 0; mm < 2; ++mm) {
        int row0 = m0 + mw + mm * 16 + g;
        #pragma unroll
        for (int nt = 0; nt < 8; ++nt) {
            int col = n0 + nw + nt * 8 + t * 2;
            float b0 = bias[col], b1 = bias[col + 1];
            float v00 = acc[mm][nt][0] + b0, v01 = acc[mm][nt][1] + b1;
            float v10 = acc[mm][nt][2] + b0, v11 = acc[mm][nt][3] + b1;
            if (OMODE == 1) {
                *reinterpret_cast<uint32_t*>(&Cg[(size_t)row0 * CD + col]) =
                    pack_f16(v00, v01);
                *reinterpret_cast<uint32_t*>(&Cg[(size_t)(row0 + 8) * CD + col]) =
                    pack_f16(v10, v11);
            } else {
                *reinterpret_cast<float2*>(&Cf[(size_t)row0 * CD + col]) =
                    make_float2(v00, v01);
                *reinterpret_cast<float2*>(&Cf[(size_t)(row0 + 8) * CD + col]) =
                    make_float2(v10, v11);
            }
        }
    }
}

// ---------------------------------------------------------------------------
// fp16 HMMA flash attention (single product), fp16 context output.
// Grid (16 q-tiles, 64 bh). 256 threads = 8 warps; warp w owns q rows w*16..+15.
// smem: Q 16KB + 2 stages x (K 8KB + V 8KB) = 48KB.
// ---------------------------------------------------------------------------
constexpr int ASMEM = 16384 + 2 * 16384;   // 49152

__global__ __launch_bounds__(256) void attn_f16(
    const __half* __restrict__ Qf, const __half* __restrict__ Kf,
    const __half* __restrict__ Vf, __half* __restrict__ Cg)
{
    extern __shared__ char smem[];
    const uint32_t sb = smem_to_u32(smem);
    const uint32_t smQ = sb;
    const int tid = threadIdx.x, lane = tid & 31, wid = tid >> 5;
    const int q0 = blockIdx.x * 128;
    const int b = blockIdx.y >> 4, h = blockIdx.y & 15;
    const size_t tbase = (size_t)b * CS * CD + (size_t)h * CE;

    const __half* qt = Qf + tbase + (size_t)q0 * CD;

    auto issueKV = [&](int kc) {
        int kt0 = kc * 64;
        uint32_t st = sb + 16384 + (uint32_t)(kc & 1) * 16384;
        const __half* kp = Kf + tbase + (size_t)kt0 * CD;
        const __half* vp = Vf + tbase + (size_t)kt0 * CD;
        #pragma unroll
        for (int j = 0; j < 2; ++j) {
            int idx = tid + j * 256, r = idx >> 3, u = idx & 7;
            cpasync16(st + swofs(r, u), kp + (size_t)r * CD + u * 8);
            cpasync16(st + 8192 + swofs(r, u), vp + (size_t)r * CD + u * 8);
        }
        CP_COMMIT();
    };

    #pragma unroll
    for (int j = 0; j < 4; ++j) {
        int idx = tid + j * 256, r = idx >> 3, u = idx & 7;
        cpasync16(smQ + swofs(r, u), qt + (size_t)r * CD + u * 8);
    }
    issueKV(0);

    float oacc[8][4];
    #pragma unroll
    for (int j = 0; j < 8; j++)
        #pragma unroll
        for (int c = 0; c < 4; c++) oacc[j][c] = 0.0f;
    float m0r = -1e30f, m1r = -1e30f, l0r = 0.0f, l1r = 0.0f;

    for (int kc = 0; kc < 32; ++kc) {
        if (kc + 1 < 32) { issueKV(kc + 1); CP_WAIT(1); }
        else { CP_WAIT(0); }
        __syncthreads();

        uint32_t st = sb + 16384 + (uint32_t)(kc & 1) * 16384;
        uint32_t stK = st, stV = st + 8192;

        // ---- S = Q K^T ----
        float sacc[8][4];
        #pragma unroll
        for (int j = 0; j < 8; j++)
            #pragma unroll
            for (int c = 0; c < 4; c++) sacc[j][c] = 0.0f;

        #pragma unroll
        for (int ks = 0; ks < 4; ++ks) {
            uint32_t afr[4];
            int ar = wid * 16 + (lane & 15);
            int au = ks * 2 + (lane >> 4);
            ldsm4(afr, smQ + swofs(ar, au));
            #pragma unroll
            for (int bn = 0; bn < 4; ++bn) {
                int br = bn * 16 + (lane & 7) + ((lane >> 4) << 3);
                int bu = ks * 2 + ((lane >> 3) & 1);
                uint32_t bfr[4];
                ldsm4(bfr, stK + swofs(br, bu));
                mma16816h(sacc[2 * bn],     afr, bfr[0], bfr[1]);
                mma16816h(sacc[2 * bn + 1], afr, bfr[2], bfr[3]);
            }
        }
        #pragma unroll
        for (int j = 0; j < 8; j++)
            #pragma unroll
            for (int c = 0; c < 4; c++) sacc[j][c] *= 0.125f;

        // ---- online softmax ----
        float mx0 = -1e30f, mx1 = -1e30f;
        #pragma unroll
        for (int j = 0; j < 8; j++) {
            mx0 = fmaxf(mx0, fmaxf(sacc[j][0], sacc[j][1]));
            mx1 = fmaxf(mx1, fmaxf(sacc[j][2], sacc[j][3]));
        }
        mx0 = fmaxf(mx0, __shfl_xor_sync(0xffffffffu, mx0, 1));
        mx0 = fmaxf(mx0, __shfl_xor_sync(0xffffffffu, mx0, 2));
        mx1 = fmaxf(mx1, __shfl_xor_sync(0xffffffffu, mx1, 1));
        mx1 = fmaxf(mx1, __shfl_xor_sync(0xffffffffu, mx1, 2));

        float mn0 = fmaxf(m0r, mx0), mn1 = fmaxf(m1r, mx1);
        float a0 = __expf(m0r - mn0), a1 = __expf(m1r - mn1);
        float s0 = 0.0f, s1 = 0.0f;
        #pragma unroll
        for (int j = 0; j < 8; j++) {
            sacc[j][0] = __expf(sacc[j][0] - mn0);
            sacc[j][1] = __expf(sacc[j][1] - mn0);
            sacc[j][2] = __expf(sacc[j][2] - mn1);
            sacc[j][3] = __expf(sacc[j][3] - mn1);
            s0 += sacc[j][0] + sacc[j][1];
            s1 += sacc[j][2] + sacc[j][3];
        }
        s0 += __shfl_xor_sync(0xffffffffu, s0, 1);
        s0 += __shfl_xor_sync(0xffffffffu, s0, 2);
        s1 += __shfl_xor_sync(0xffffffffu, s1, 1);
        s1 += __shfl_xor_sync(0xffffffffu, s1, 2);
        l0r = l0r * a0 + s0;
        l1r = l1r * a1 + s1;
        m0r = mn0; m1r = mn1;
        #pragma unroll
        for (int j = 0; j < 8; j++) {
            oacc[j][0] *= a0; oacc[j][1] *= a0;
            oacc[j][2] *= a1; oacc[j][3] *= a1;
        }

        // ---- O += P V ----
        #pragma unroll
        for (int kj = 0; kj < 4; ++kj) {
            uint32_t p[4];
            p[0] = pack_f16(sacc[2 * kj][0],     sacc[2 * kj][1]);
            p[1] = pack_f16(sacc[2 * kj][2],     sacc[2 * kj][3]);
            p[2] = pack_f16(sacc[2 * kj + 1][0], sacc[2 * kj + 1][1]);
            p[3] = pack_f16(sacc[2 * kj + 1][2], sacc[2 * kj + 1][3]);
            #pragma unroll
            for (int en = 0; en < 4; ++en) {
                int vr = kj * 16 + (lane & 7) + (((lane >> 3) & 1) << 3);
                int vu = en * 2 + (lane >> 4);
                uint32_t vfr[4];
                ldsm4t(vfr, stV + swofs(vr, vu));
                mma16816h(oacc[2 * en],     p, vfr[0], vfr[1]);
                mma16816h(oacc[2 * en + 1], p, vfr[2], vfr[3]);
            }
        }
        __syncthreads();
    }

    // ---- epilogue: normalize, fp16 store ----
    const float inv0 = 1.0f / l0r, inv1 = 1.0f / l1r;
    const int g = lane >> 2, t = lane & 3;
    const int row0 = q0 + wid * 16 + g;
    #pragma unroll
    for (int nt = 0; nt < 8; ++nt) {
        int col = nt * 8 + t * 2;
        *reinterpret_cast<uint32_t*>(&Cg[tbase + (size_t)row0 * CD + col]) =
            pack_f16(oacc[nt][0] * inv0, oacc[nt][1] * inv0);
        *reinterpret_cast<uint32_t*>(&Cg[tbase + (size_t)(row0 + 8) * CD + col]) =
            pack_f16(oacc[nt][2] * inv1, oacc[nt][3] * inv1);
    }
}

// ---------------------------------------------------------------------------
// Launch
// ---------------------------------------------------------------------------
extern "C" void kernel_launch(void* const* d_in, const int* in_sizes, int n_in,
                              void* d_out, int out_size)
{
    const float* query = (const float*)d_in[0];
    const float* key   = (const float*)d_in[1];
    const float* value = (const float*)d_in[2];
    const float* wq    = (const float*)d_in[3];
    const float* bq    = (const float*)d_in[4];
    const float* wk    = (const float*)d_in[5];
    const float* bk    = (const float*)d_in[6];
    const float* wv    = (const float*)d_in[7];
    const float* bv    = (const float*)d_in[8];
    const float* wo    = (const float*)d_in[9];
    const float* bo    = (const float*)d_in[10];
    float* out = (float*)d_out;

    __half *xq,*xk,*xv,*wq16,*wk16,*wv16,*wo16,*qf,*kf,*vf,*cf;
    cudaGetSymbolAddress((void**)&xq, g_xq);
    cudaGetSymbolAddress((void**)&xk, g_xk);
    cudaGetSymbolAddress((void**)&xv, g_xv);
    cudaGetSymbolAddress((void**)&wq16, g_wq16);
    cudaGetSymbolAddress((void**)&wk16, g_wk16);
    cudaGetSymbolAddress((void**)&wv16, g_wv16);
    cudaGetSymbolAddress((void**)&wo16, g_wo16);
    cudaGetSymbolAddress((void**)&qf, g_qf);
    cudaGetSymbolAddress((void**)&kf, g_kf);
    cudaGetSymbolAddress((void**)&vf, g_vf);
    cudaGetSymbolAddress((void**)&cf, g_cf);

    cudaFuncSetAttribute(gemm_f16<0>,
                         cudaFuncAttributeMaxDynamicSharedMemorySize, GSMEM);
    cudaFuncSetAttribute(gemm_f16<1>,
                         cudaFuncAttributeMaxDynamicSharedMemorySize, GSMEM);
    cudaFuncSetAttribute(attn_f16,
                         cudaFuncAttributeMaxDynamicSharedMemorySize, ASMEM);

    const int nBig = MROWS * CD / 4;   // 2M float4
    const int nW   = CD * CD / 4;      // 256K float4

    conv16_kernel<<<nBig / 256, 256>>>(query, xq, nBig);
    conv16_kernel<<<nBig / 256, 256>>>(key,   xk, nBig);
    conv16_kernel<<<nBig / 256, 256>>>(value, xv, nBig);
    conv16_kernel<<<nW / 256, 256>>>(wq, wq16, nW);
    conv16_kernel<<<nW / 256, 256>>>(wk, wk16, nW);
    conv16_kernel<<<nW / 256, 256>>>(wv, wv16, nW);
    conv16_kernel<<<nW / 256, 256>>>(wo, wo16, nW);

    dim3 ggrid(CD / 128, MROWS / 128);  // (8, 64)
    gemm_f16<1><<<ggrid, 256, GSMEM>>>(xq, wq16, bq, nullptr, qf);
    gemm_f16<1><<<ggrid, 256, GSMEM>>>(xk, wk16, bk, nullptr, kf);
    gemm_f16<1><<<ggrid, 256, GSMEM>>>(xv, wv16, bv, nullptr, vf);

    attn_f16<<<dim3(CS / 128, CB * CH), 256, ASMEM>>>(qf, kf, vf, cf);

    gemm_f16<0><<<ggrid, 256, GSMEM>>>(cf, wo16, bo, out, nullptr);
}